// round 16
// baseline (speedup 1.0000x reference)
#include <cuda_runtime.h>
#include <cuda_fp16.h>
#include <cstdint>

typedef __half f16;

// ---------------- scratch ----------------
__device__ f16 g_A1 [256 * 4096];
__device__ f16 g_A2 [256 * 4096];
__device__ f16 g_A3 [256 * 4096];
__device__ f16 g_W1h[4096u * 4096u];      // k-major, same layout as W1
__device__ f16 g_W2h[4096u * 4096u];
__device__ f16 g_W3h[4096 * 256];         // k-major, n padded 200->256
__device__ float g_pb [4 * 256 * 4096];
__device__ float g_p3 [32 * 256 * 256];

// ---------------- helpers ----------------
__device__ __forceinline__ float sig_apx(float a) {
    float r; asm("tanh.approx.f32 %0,%1;" : "=f"(r) : "f"(a * 0.5f));
    return fmaf(0.5f, r, 0.5f);
}
__device__ __forceinline__ void mma16816(float* c, const uint32_t* a, const uint32_t* b) {
    asm volatile("mma.sync.aligned.m16n8k16.row.col.f32.f16.f16.f32 "
        "{%0,%1,%2,%3}, {%4,%5,%6,%7}, {%8,%9}, {%0,%1,%2,%3};"
        : "+f"(c[0]), "+f"(c[1]), "+f"(c[2]), "+f"(c[3])
        : "r"(a[0]), "r"(a[1]), "r"(a[2]), "r"(a[3]), "r"(b[0]), "r"(b[1]));
}
__device__ __forceinline__ void ldsm4(uint32_t* r, uint32_t addr) {
    asm volatile("ldmatrix.sync.aligned.m8n8.x4.shared.b16 {%0,%1,%2,%3}, [%4];"
        : "=r"(r[0]), "=r"(r[1]), "=r"(r[2]), "=r"(r[3]) : "r"(addr));
}
__device__ __forceinline__ void ldsm4t(uint32_t* r, uint32_t addr) {
    asm volatile("ldmatrix.sync.aligned.m8n8.x4.trans.shared.b16 {%0,%1,%2,%3}, [%4];"
        : "=r"(r[0]), "=r"(r[1]), "=r"(r[2]), "=r"(r[3]) : "r"(addr));
}
__device__ __forceinline__ void cpasync16(uint32_t dst, const void* src) {
    asm volatile("cp.async.cg.shared.global [%0], [%1], 16;" :: "r"(dst), "l"(src) : "memory");
}
__device__ __forceinline__ void cpcommit() {
    asm volatile("cp.async.commit_group;" ::: "memory");
}
template<int N> __device__ __forceinline__ void cpwait() {
    asm volatile("cp.async.wait_group %0;" :: "n"(N) : "memory");
}

// ---------------- ECT body (256 threads, 4 node-quarters) ----------------
struct EctSm {
    float xs[200];
    float Vs[128];
    float lins[64];
    float e2[4][4096];
    unsigned char cnt2[4][4096];
    float red[256];
};
#define PREP_SMEM (sizeof(EctSm))

// If P != nullptr: points come from split-K partials (sum 32 planes + bias),
// and are also written to otail. Else points come from ptsg (fp32 [g][100][2]).
__device__ void ect_body(int g, int tid, const float* __restrict__ ptsg,
                         const float* __restrict__ P, const float* __restrict__ b3,
                         float* __restrict__ otail,
                         const float* __restrict__ V, const float* __restrict__ lin,
                         float* __restrict__ outf, f16* __restrict__ outh, char* sm)
{
    EctSm& S = *reinterpret_cast<EctSm*>(sm);
    if (tid < 64)  S.lins[tid] = lin[tid];
    if (tid < 128) S.Vs[tid] = V[tid];
    if (P) {
        if (tid < 200) {
            float s = b3[tid];
            #pragma unroll
            for (int zz = 0; zz < 32; ++zz) s += P[zz * 65536 + g * 256 + tid];
            S.xs[tid] = s;
            otail[g * 200 + tid] = s;
        }
    } else if (tid < 100) {
        float2 p = reinterpret_cast<const float2*>(ptsg)[g * 100 + tid];
        S.xs[2 * tid] = p.x; S.xs[2 * tid + 1] = p.y;
    }
    for (int i = tid; i < 16384; i += 256) (&S.e2[0][0])[i] = 0.0f;
    for (int i = tid; i < 4096; i += 256) reinterpret_cast<int*>(S.cnt2)[i] = 0;
    __syncthreads();

    {
        const int t = tid & 63, q = tid >> 6;
        const float vx = S.Vs[t], vy = S.Vs[64 + t];
        float* e = &S.e2[q][t];
        unsigned char* cc = &S.cnt2[q][t];
        const int nbeg = q * 25;
        for (int n = 0; n < 25; ++n) {
            const float x0 = S.xs[2 * (nbeg + n)], x1 = S.xs[2 * (nbeg + n) + 1];
            const float nh = fmaf(x0, vx, x1 * vy);
            const int kf = __float2int_rd((nh + 1.0f) * 31.5f);
            if (kf >= 0 && kf < 64)         e[kf * 64]       += sig_apx(500.0f * (S.lins[kf] - nh));
            if (kf + 1 >= 0 && kf + 1 < 64) e[(kf + 1) * 64] += sig_apx(500.0f * (S.lins[kf + 1] - nh));
            int s = kf + 2; if (s < 0) s = 0;
            if (s < 64) cc[s * 64] = (unsigned char)(cc[s * 64] + 1);
        }
    }
    __syncthreads();

    if (tid < 64) {
        float run = 0.0f;
        for (int k = 0; k < 64; ++k) {
            const int o = k * 64 + tid;
            run += (float)(S.cnt2[0][o] + S.cnt2[1][o] + S.cnt2[2][o] + S.cnt2[3][o]);
            S.e2[0][o] = S.e2[0][o] + S.e2[1][o] + S.e2[2][o] + S.e2[3][o] + run;
        }
    }
    __syncthreads();

    float mx = 0.0f;
    for (int i = tid; i < 4096; i += 256) mx = fmaxf(mx, S.e2[0][i]);
    S.red[tid] = mx; __syncthreads();
    for (int off = 128; off > 0; off >>= 1) {
        if (tid < off) S.red[tid] = fmaxf(S.red[tid], S.red[tid + off]);
        __syncthreads();
    }
    const float inv = 1.0f / S.red[0];
    for (int i = tid; i < 4096; i += 256) {
        float v = S.e2[0][i] * inv;
        if (outf) outf[(long)g * 4096 + i] = v;
        if (outh) outh[(long)g * 4096 + i] = __float2half_rn(v);
    }
}

// ---------------- streaming fp32 -> fp16 (no transpose) ----------------
__device__ void convert_body(const float* __restrict__ W, f16* __restrict__ Th, int b)
{
    #pragma unroll
    for (int p = 0; p < 4; ++p) {
        const long o = ((long)b * 1024 + p * 256 + threadIdx.x) * 8;
        float4 v0 = *reinterpret_cast<const float4*>(W + o);
        float4 v1 = *reinterpret_cast<const float4*>(W + o + 4);
        __half2 h[4];
        h[0] = __floats2half2_rn(v0.x, v0.y);
        h[1] = __floats2half2_rn(v0.z, v0.w);
        h[2] = __floats2half2_rn(v1.x, v1.y);
        h[3] = __floats2half2_rn(v1.z, v1.w);
        *reinterpret_cast<uint4*>(Th + o) = *reinterpret_cast<uint4*>(h);
    }
}

__device__ void convertw3_body(const float* __restrict__ W3, f16* __restrict__ Th, int b)
{
    #pragma unroll
    for (int p = 0; p < 16; ++p) {
        const int i = b * 4096 + p * 256 + threadIdx.x;
        const int k = i >> 8, n = i & 255;
        Th[i] = __float2half_rn((n < 200) ? W3[k * 200 + n] : 0.0f);
    }
}

// ---------------- fused prep: stream-convert W1/W2/W3 + ect1 ----------------
__global__ void __launch_bounds__(256) prep_all(const float* __restrict__ x,
    const float* __restrict__ V, const float* __restrict__ lin,
    const float* __restrict__ W1, const float* __restrict__ W2, const float* __restrict__ W3,
    f16* W1h, f16* W2h, f16* W3h, f16* A1)
{
    extern __shared__ char sm[];
    int b = blockIdx.x;
    if (b < 2048)       convert_body(W1, W1h, b);
    else if (b < 4096)  convert_body(W2, W2h, b - 2048);
    else if (b < 4352)  convertw3_body(W3, W3h, b - 4096);
    else                ect_body(b - 4352, threadIdx.x, x, nullptr, nullptr, nullptr,
                                 V, lin, nullptr, A1, sm);
}

// final ECT fused with split-K reduce of GEMM3
__global__ void __launch_bounds__(256) ect_final(const float* __restrict__ P,
    const float* __restrict__ b3, const float* __restrict__ V,
    const float* __restrict__ lin, float* __restrict__ out)
{
    extern __shared__ char sm[];
    ect_body(blockIdx.x, threadIdx.x, nullptr, P, b3, out + 256 * 64 * 64,
             V, lin, out, nullptr, sm);
}

// ---------------- HMMA GEMM: CTA 128x128, warp 32x64, frag double-buffer ----------------
// A smem [128 m][64 k] rows 128B, swizzle (kq*16)^((m&7)<<4).
// B smem [64 k][128 n] rows 256B, swizzle (c*16)^((k&7)<<4).
// 3-stage cp.async race-free + register fragment ping-pong across ks.
#define STG 32768
#define NSTAGE 3
#define GMEM_SM (NSTAGE * STG)

template<int KT>
__global__ void __launch_bounds__(256, 2) gemm_mma(const f16* __restrict__ A,
                                                   const f16* __restrict__ B,
                                                   float* __restrict__ P,
                                                   int Nout, int strideB)
{
    extern __shared__ __align__(16) char dsm[];
    const uint32_t smem0 = (uint32_t)__cvta_generic_to_shared(dsm);
    const int tid = threadIdx.x;
    const int lane = tid & 31, wid = tid >> 5;
    const int wm = wid >> 1, wn = wid & 1;
    const int m0 = blockIdx.x * 128, n0 = blockIdx.y * 128;
    const long kOff = (long)blockIdx.z * (KT * 64);

    const int rA = tid >> 3, kq = tid & 7;
    const uint32_t dswA = (uint32_t)(rA * 128 + ((kq * 16) ^ ((rA & 7) << 4)));
    const f16* pA = A + (long)(m0 + rA) * 4096 + kOff + kq * 8;

    const int rB = tid >> 4, cnB = tid & 15;
    const f16* pB = B + (long)rB * strideB + n0 + cnB * 8;

    float acc[2][8][4];
    #pragma unroll
    for (int a = 0; a < 2; ++a)
        #pragma unroll
        for (int b = 0; b < 8; ++b)
            #pragma unroll
            for (int c = 0; c < 4; ++c) acc[a][b][c] = 0.0f;

    const int lr = lane & 7, lt = lane >> 3;
    const uint32_t aRow = (uint32_t)((wm * 32 + ((lt & 1) << 3) + lr) * 128);
    const int aK = (lt >> 1) * 16;
    const int swA = lr << 4;
    const int bH = (lt & 1) * 8 + lr;
    const int bC0 = wn * 8 + (lt >> 1);

    auto load_stage = [&](int stg, int kt) {
        const uint32_t st = smem0 + stg * STG;
        const long gk = kOff + (long)kt * 64;
        #pragma unroll
        for (int i = 0; i < 4; ++i)
            cpasync16(st + dswA + i * 32 * 128, pA + (long)kt * 64 + (long)i * 32 * 4096);
        #pragma unroll
        for (int p = 0; p < 4; ++p) {
            const int krow = p * 16 + rB;
            const uint32_t d = st + 16384 + (uint32_t)krow * 256
                             + (uint32_t)(((cnB * 16) ^ ((krow & 7) << 4)));
            cpasync16(d, pB + (gk + p * 16) * (long)strideB);
        }
    };

    #pragma unroll
    for (int s = 0; s < NSTAGE - 1; ++s) {
        if (s < KT) load_stage(s % NSTAGE, s);
        cpcommit();
    }

    uint32_t fA[2][2][4], fB[2][4][4];

    for (int kt = 0; kt < KT; ++kt) {
        cpwait<NSTAGE - 2>();
        __syncthreads();
        if (kt + NSTAGE - 1 < KT)
            load_stage((kt + NSTAGE - 1) % NSTAGE, kt + NSTAGE - 1);
        cpcommit();

        const uint32_t st = smem0 + (kt % NSTAGE) * STG;

        // fragment loader for a given ks into buffer buf
        auto ldfrag = [&](int ks, int buf) {
            const int ka = (ks * 32 + aK) ^ swA;
            const int krow = ks * 16 + bH;
            ldsm4(fA[buf][0], st + aRow + ka);
            ldsm4(fA[buf][1], st + aRow + 16 * 128 + ka);
            #pragma unroll
            for (int j = 0; j < 4; ++j) {
                const uint32_t bAddr = st + 16384 + (uint32_t)krow * 256
                    + (uint32_t)((((bC0 + 2 * j) * 16) ^ ((krow & 7) << 4)));
                ldsm4t(fB[buf][j], bAddr);
            }
        };

        ldfrag(0, 0);
        #pragma unroll
        for (int ks = 0; ks < 4; ++ks) {
            const int cur = ks & 1;
            if (ks < 3) ldfrag(ks + 1, cur ^ 1);
            #pragma unroll
            for (int mt = 0; mt < 2; ++mt)
                #pragma unroll
                for (int nt = 0; nt < 8; ++nt) {
                    const uint32_t* b = &fB[cur][nt >> 1][(nt & 1) * 2];
                    mma16816(acc[mt][nt], fA[cur][mt], b);
                }
        }
    }

    const int laneR = lane >> 2;
    float* Pz = P + (long)blockIdx.z * 256 * Nout;
    #pragma unroll
    for (int mt = 0; mt < 2; ++mt)
        #pragma unroll
        for (int nt = 0; nt < 8; ++nt) {
            const int rr = m0 + wm * 32 + mt * 16 + laneR;
            const int nc = n0 + wn * 64 + nt * 8 + 2 * (lane & 3);
            *(float2*)(Pz + (long)rr * Nout + nc)       = make_float2(acc[mt][nt][0], acc[mt][nt][1]);
            *(float2*)(Pz + (long)(rr + 8) * Nout + nc) = make_float2(acc[mt][nt][2], acc[mt][nt][3]);
        }
}

// ---------------- reduce: 4 partials + bias -> tanh -> f16 ----------------
__global__ void reduce_tanh(const float* __restrict__ P, const float* __restrict__ bias,
                            f16* __restrict__ outh)
{
    const int i = blockIdx.x * 256 + threadIdx.x;
    float s = bias[i & 4095] + P[i] + P[1048576 + i] + P[2097152 + i] + P[3145728 + i];
    outh[i] = __float2half_rn(tanhf(s));
}

// ---------------- launch ----------------
extern "C" void kernel_launch(void* const* d_in, const int* in_sizes, int n_in,
                              void* d_out, int out_size)
{
    const float* x   = (const float*)d_in[0];
    const float* V   = (const float*)d_in[2];
    const float* lin = (const float*)d_in[3];
    const float* W1  = (const float*)d_in[4];
    const float* b1  = (const float*)d_in[5];
    const float* W2  = (const float*)d_in[6];
    const float* b2  = (const float*)d_in[7];
    const float* W3  = (const float*)d_in[8];
    const float* b3  = (const float*)d_in[9];
    float* out = (float*)d_out;

    f16 *A1, *A2, *A3, *W1h, *W2h, *W3h;
    float *pb, *p3;
    cudaGetSymbolAddress((void**)&A1,  g_A1);
    cudaGetSymbolAddress((void**)&A2,  g_A2);
    cudaGetSymbolAddress((void**)&A3,  g_A3);
    cudaGetSymbolAddress((void**)&W1h, g_W1h);
    cudaGetSymbolAddress((void**)&W2h, g_W2h);
    cudaGetSymbolAddress((void**)&W3h, g_W3h);
    cudaGetSymbolAddress((void**)&pb,  g_pb);
    cudaGetSymbolAddress((void**)&p3,  g_p3);

    const int prep_sm = (int)PREP_SMEM;
    cudaFuncSetAttribute(prep_all,  cudaFuncAttributeMaxDynamicSharedMemorySize, prep_sm);
    cudaFuncSetAttribute(ect_final, cudaFuncAttributeMaxDynamicSharedMemorySize, prep_sm);
    cudaFuncSetAttribute(gemm_mma<16>, cudaFuncAttributeMaxDynamicSharedMemorySize, GMEM_SM);
    cudaFuncSetAttribute(gemm_mma<2>,  cudaFuncAttributeMaxDynamicSharedMemorySize, GMEM_SM);

    prep_all<<<4608, 256, prep_sm>>>(x, V, lin, W1, W2, W3, W1h, W2h, W3h, A1);

    gemm_mma<16><<<dim3(2, 32, 4), 256, GMEM_SM>>>(A1, W1h, pb, 4096, 4096);
    reduce_tanh<<<4096, 256>>>(pb, b1, A2);
    gemm_mma<16><<<dim3(2, 32, 4), 256, GMEM_SM>>>(A2, W2h, pb, 4096, 4096);
    reduce_tanh<<<4096, 256>>>(pb, b2, A3);
    gemm_mma<2><<<dim3(2, 2, 32), 256, GMEM_SM>>>(A3, W3h, p3, 256, 256);

    ect_final<<<256, 256, prep_sm>>>(p3, b3, V, lin, out);
}

// round 17
// speedup vs baseline: 1.0738x; 1.0738x over previous
#include <cuda_runtime.h>
#include <cuda_fp16.h>
#include <cstdint>

typedef __half f16;

// ---------------- scratch ----------------
__device__ f16 g_A1 [256 * 4096];
__device__ f16 g_A2 [256 * 4096];
__device__ f16 g_A3 [256 * 4096];
__device__ f16 g_W1h[4096u * 4096u];      // k-major, same layout as W1
__device__ f16 g_W2h[4096u * 4096u];
__device__ f16 g_W3h[4096 * 256];         // k-major, n padded 200->256
__device__ float g_pb [4 * 256 * 4096];
__device__ float g_p3 [32 * 256 * 256];

// ---------------- helpers ----------------
__device__ __forceinline__ float sig_apx(float a) {
    float r; asm("tanh.approx.f32 %0,%1;" : "=f"(r) : "f"(a * 0.5f));
    return fmaf(0.5f, r, 0.5f);
}
__device__ __forceinline__ void mma16816(float* c, const uint32_t* a, const uint32_t* b) {
    asm volatile("mma.sync.aligned.m16n8k16.row.col.f32.f16.f16.f32 "
        "{%0,%1,%2,%3}, {%4,%5,%6,%7}, {%8,%9}, {%0,%1,%2,%3};"
        : "+f"(c[0]), "+f"(c[1]), "+f"(c[2]), "+f"(c[3])
        : "r"(a[0]), "r"(a[1]), "r"(a[2]), "r"(a[3]), "r"(b[0]), "r"(b[1]));
}
__device__ __forceinline__ void ldsm4(uint32_t* r, uint32_t addr) {
    asm volatile("ldmatrix.sync.aligned.m8n8.x4.shared.b16 {%0,%1,%2,%3}, [%4];"
        : "=r"(r[0]), "=r"(r[1]), "=r"(r[2]), "=r"(r[3]) : "r"(addr));
}
__device__ __forceinline__ void ldsm4t(uint32_t* r, uint32_t addr) {
    asm volatile("ldmatrix.sync.aligned.m8n8.x4.trans.shared.b16 {%0,%1,%2,%3}, [%4];"
        : "=r"(r[0]), "=r"(r[1]), "=r"(r[2]), "=r"(r[3]) : "r"(addr));
}
__device__ __forceinline__ void cpasync16(uint32_t dst, const void* src) {
    asm volatile("cp.async.cg.shared.global [%0], [%1], 16;" :: "r"(dst), "l"(src) : "memory");
}
__device__ __forceinline__ void cpcommit() {
    asm volatile("cp.async.commit_group;" ::: "memory");
}
template<int N> __device__ __forceinline__ void cpwait() {
    asm volatile("cp.async.wait_group %0;" :: "n"(N) : "memory");
}

// ---------------- ECT body (256 threads, 4 node-quarters) ----------------
struct EctSm {
    float xs[200];
    float Vs[128];
    float lins[64];
    float e2[4][4096];
    unsigned char cnt2[4][4096];
    float red[256];
};
#define PREP_SMEM (sizeof(EctSm))

// If P != nullptr: points = sum of 32 split-K planes + bias, also written to otail.
__device__ void ect_body(int g, int tid, const float* __restrict__ ptsg,
                         const float* __restrict__ P, const float* __restrict__ b3,
                         float* __restrict__ otail,
                         const float* __restrict__ V, const float* __restrict__ lin,
                         float* __restrict__ outf, f16* __restrict__ outh, char* sm)
{
    EctSm& S = *reinterpret_cast<EctSm*>(sm);
    if (tid < 64)  S.lins[tid] = lin[tid];
    if (tid < 128) S.Vs[tid] = V[tid];
    if (P) {
        if (tid < 200) {
            float s = b3[tid];
            #pragma unroll
            for (int zz = 0; zz < 32; ++zz) s += P[zz * 65536 + g * 256 + tid];
            S.xs[tid] = s;
            otail[g * 200 + tid] = s;
        }
    } else if (tid < 100) {
        float2 p = reinterpret_cast<const float2*>(ptsg)[g * 100 + tid];
        S.xs[2 * tid] = p.x; S.xs[2 * tid + 1] = p.y;
    }
    for (int i = tid; i < 16384; i += 256) (&S.e2[0][0])[i] = 0.0f;
    for (int i = tid; i < 4096; i += 256) reinterpret_cast<int*>(S.cnt2)[i] = 0;
    __syncthreads();

    {
        const int t = tid & 63, q = tid >> 6;
        const float vx = S.Vs[t], vy = S.Vs[64 + t];
        float* e = &S.e2[q][t];
        unsigned char* cc = &S.cnt2[q][t];
        const int nbeg = q * 25;
        for (int n = 0; n < 25; ++n) {
            const float x0 = S.xs[2 * (nbeg + n)], x1 = S.xs[2 * (nbeg + n) + 1];
            const float nh = fmaf(x0, vx, x1 * vy);
            const int kf = __float2int_rd((nh + 1.0f) * 31.5f);
            if (kf >= 0 && kf < 64)         e[kf * 64]       += sig_apx(500.0f * (S.lins[kf] - nh));
            if (kf + 1 >= 0 && kf + 1 < 64) e[(kf + 1) * 64] += sig_apx(500.0f * (S.lins[kf + 1] - nh));
            int s = kf + 2; if (s < 0) s = 0;
            if (s < 64) cc[s * 64] = (unsigned char)(cc[s * 64] + 1);
        }
    }
    __syncthreads();

    if (tid < 64) {
        float run = 0.0f;
        for (int k = 0; k < 64; ++k) {
            const int o = k * 64 + tid;
            run += (float)(S.cnt2[0][o] + S.cnt2[1][o] + S.cnt2[2][o] + S.cnt2[3][o]);
            S.e2[0][o] = S.e2[0][o] + S.e2[1][o] + S.e2[2][o] + S.e2[3][o] + run;
        }
    }
    __syncthreads();

    float mx = 0.0f;
    for (int i = tid; i < 4096; i += 256) mx = fmaxf(mx, S.e2[0][i]);
    S.red[tid] = mx; __syncthreads();
    for (int off = 128; off > 0; off >>= 1) {
        if (tid < off) S.red[tid] = fmaxf(S.red[tid], S.red[tid + off]);
        __syncthreads();
    }
    const float inv = 1.0f / S.red[0];
    for (int i = tid; i < 4096; i += 256) {
        float v = S.e2[0][i] * inv;
        if (outf) outf[(long)g * 4096 + i] = v;
        if (outh) outh[(long)g * 4096 + i] = __float2half_rn(v);
    }
}

// ---------------- streaming fp32 -> fp16 (8192 floats per call) ----------------
__device__ void convert_body(const float* __restrict__ W, f16* __restrict__ Th, int b)
{
    #pragma unroll
    for (int p = 0; p < 4; ++p) {
        const long o = ((long)b * 1024 + p * 256 + threadIdx.x) * 8;
        float4 v0 = *reinterpret_cast<const float4*>(W + o);
        float4 v1 = *reinterpret_cast<const float4*>(W + o + 4);
        __half2 h[4];
        h[0] = __floats2half2_rn(v0.x, v0.y);
        h[1] = __floats2half2_rn(v0.z, v0.w);
        h[2] = __floats2half2_rn(v1.x, v1.y);
        h[3] = __floats2half2_rn(v1.z, v1.w);
        *reinterpret_cast<uint4*>(Th + o) = *reinterpret_cast<uint4*>(h);
    }
}

__device__ void convertw3_body(const float* __restrict__ W3, f16* __restrict__ Th, int b)
{
    #pragma unroll
    for (int p = 0; p < 16; ++p) {
        const int i = b * 4096 + p * 256 + threadIdx.x;   // b in [0,256)
        const int k = i >> 8, n = i & 255;
        Th[i] = __float2half_rn((n < 200) ? W3[k * 200 + n] : 0.0f);
    }
}

// ---------------- prep: W1 convert + ect1 ----------------
__global__ void __launch_bounds__(256) prep_all(const float* __restrict__ x,
    const float* __restrict__ V, const float* __restrict__ lin,
    const float* __restrict__ W1, f16* W1h, f16* A1)
{
    extern __shared__ char sm[];
    int b = blockIdx.x;
    if (b < 2048) convert_body(W1, W1h, b);
    else          ect_body(b - 2048, threadIdx.x, x, nullptr, nullptr, nullptr,
                           V, lin, nullptr, A1, sm);
}

// final ECT fused with split-K reduce of GEMM3
__global__ void __launch_bounds__(256) ect_final(const float* __restrict__ P,
    const float* __restrict__ b3, const float* __restrict__ V,
    const float* __restrict__ lin, float* __restrict__ out)
{
    extern __shared__ char sm[];
    ect_body(blockIdx.x, threadIdx.x, nullptr, P, b3, out + 256 * 64 * 64,
             V, lin, out, nullptr, sm);
}

// ---------------- HMMA GEMM (+ optional piggybacked W2/W3 conversion) ----------------
// 1-D grid, first nGemm blocks decode to (bx,by,bz); blocks past nGemm stream-convert.
// A smem [128 m][64 k] rows 128B, swizzle (kq*16)^((m&7)<<4).
// B smem [64 k][128 n] rows 256B, swizzle (c*16)^((k&7)<<4). ldsm.trans B fragments.
// 3-stage cp.async race-free + register fragment ping-pong.
#define STG 32768
#define NSTAGE 3
#define GMEM_SM (NSTAGE * STG)

template<int KT, int NYB>
__global__ void __launch_bounds__(256, 2) gemm_mma(const f16* __restrict__ A,
                                                   const f16* __restrict__ B,
                                                   float* __restrict__ P,
                                                   int Nout, int strideB, int nGemm,
                                                   const float* __restrict__ Wc, f16* Wch,
                                                   const float* __restrict__ W3c, f16* W3ch)
{
    const int bid = blockIdx.x;
    if (bid >= nGemm) {               // piggybacked conversion CTAs
        int b2 = bid - nGemm;
        if (b2 < 512) {
            #pragma unroll
            for (int c = 0; c < 4; ++c) convert_body(Wc, Wch, b2 * 4 + c);
        } else {
            b2 -= 512;                // 64 blocks x 4 bodies = 256
            #pragma unroll
            for (int c = 0; c < 4; ++c) convertw3_body(W3c, W3ch, b2 * 4 + c);
        }
        return;
    }

    extern __shared__ __align__(16) char dsm[];
    const uint32_t smem0 = (uint32_t)__cvta_generic_to_shared(dsm);
    const int tid = threadIdx.x;
    const int lane = tid & 31, wid = tid >> 5;
    const int wm = wid >> 1, wn = wid & 1;
    const int bx = bid & 1, by = (bid >> 1) & ((1 << NYB) - 1), bz = bid >> (1 + NYB);
    const int m0 = bx * 128, n0 = by * 128;
    const long kOff = (long)bz * (KT * 64);

    const int rA = tid >> 3, kq = tid & 7;
    const uint32_t dswA = (uint32_t)(rA * 128 + ((kq * 16) ^ ((rA & 7) << 4)));
    const f16* pA = A + (long)(m0 + rA) * 4096 + kOff + kq * 8;

    const int rB = tid >> 4, cnB = tid & 15;
    const f16* pB = B + (long)rB * strideB + n0 + cnB * 8;

    float acc[2][8][4];
    #pragma unroll
    for (int a = 0; a < 2; ++a)
        #pragma unroll
        for (int b = 0; b < 8; ++b)
            #pragma unroll
            for (int c = 0; c < 4; ++c) acc[a][b][c] = 0.0f;

    const int lr = lane & 7, lt = lane >> 3;
    const uint32_t aRow = (uint32_t)((wm * 32 + ((lt & 1) << 3) + lr) * 128);
    const int aK = (lt >> 1) * 16;
    const int swA = lr << 4;
    const int bH = (lt & 1) * 8 + lr;
    const int bC0 = wn * 8 + (lt >> 1);

    auto load_stage = [&](int stg, int kt) {
        const uint32_t st = smem0 + stg * STG;
        const long gk = kOff + (long)kt * 64;
        #pragma unroll
        for (int i = 0; i < 4; ++i)
            cpasync16(st + dswA + i * 32 * 128, pA + (long)kt * 64 + (long)i * 32 * 4096);
        #pragma unroll
        for (int p = 0; p < 4; ++p) {
            const int krow = p * 16 + rB;
            const uint32_t d = st + 16384 + (uint32_t)krow * 256
                             + (uint32_t)(((cnB * 16) ^ ((krow & 7) << 4)));
            cpasync16(d, pB + (gk + p * 16) * (long)strideB);
        }
    };

    #pragma unroll
    for (int s = 0; s < NSTAGE - 1; ++s) {
        if (s < KT) load_stage(s % NSTAGE, s);
        cpcommit();
    }

    uint32_t fA[2][2][4], fB[2][4][4];

    for (int kt = 0; kt < KT; ++kt) {
        cpwait<NSTAGE - 2>();
        __syncthreads();
        if (kt + NSTAGE - 1 < KT)
            load_stage((kt + NSTAGE - 1) % NSTAGE, kt + NSTAGE - 1);
        cpcommit();

        const uint32_t st = smem0 + (kt % NSTAGE) * STG;

        auto ldfrag = [&](int ks, int buf) {
            const int ka = (ks * 32 + aK) ^ swA;
            const int krow = ks * 16 + bH;
            ldsm4(fA[buf][0], st + aRow + ka);
            ldsm4(fA[buf][1], st + aRow + 16 * 128 + ka);
            #pragma unroll
            for (int j = 0; j < 4; ++j) {
                const uint32_t bAddr = st + 16384 + (uint32_t)krow * 256
                    + (uint32_t)((((bC0 + 2 * j) * 16) ^ ((krow & 7) << 4)));
                ldsm4t(fB[buf][j], bAddr);
            }
        };

        ldfrag(0, 0);
        #pragma unroll
        for (int ks = 0; ks < 4; ++ks) {
            const int cur = ks & 1;
            if (ks < 3) ldfrag(ks + 1, cur ^ 1);
            #pragma unroll
            for (int mt = 0; mt < 2; ++mt)
                #pragma unroll
                for (int nt = 0; nt < 8; ++nt) {
                    const uint32_t* b = &fB[cur][nt >> 1][(nt & 1) * 2];
                    mma16816(acc[mt][nt], fA[cur][mt], b);
                }
        }
    }

    const int laneR = lane >> 2;
    float* Pz = P + (long)bz * 256 * Nout;
    #pragma unroll
    for (int mt = 0; mt < 2; ++mt)
        #pragma unroll
        for (int nt = 0; nt < 8; ++nt) {
            const int rr = m0 + wm * 32 + mt * 16 + laneR;
            const int nc = n0 + wn * 64 + nt * 8 + 2 * (lane & 3);
            *(float2*)(Pz + (long)rr * Nout + nc)       = make_float2(acc[mt][nt][0], acc[mt][nt][1]);
            *(float2*)(Pz + (long)(rr + 8) * Nout + nc) = make_float2(acc[mt][nt][2], acc[mt][nt][3]);
        }
}

// ---------------- reduce: 4 partials + bias -> tanh -> f16 ----------------
__global__ void reduce_tanh(const float* __restrict__ P, const float* __restrict__ bias,
                            f16* __restrict__ outh)
{
    const int i = blockIdx.x * 256 + threadIdx.x;
    float s = bias[i & 4095] + P[i] + P[1048576 + i] + P[2097152 + i] + P[3145728 + i];
    outh[i] = __float2half_rn(tanhf(s));
}

// ---------------- launch ----------------
extern "C" void kernel_launch(void* const* d_in, const int* in_sizes, int n_in,
                              void* d_out, int out_size)
{
    const float* x   = (const float*)d_in[0];
    const float* V   = (const float*)d_in[2];
    const float* lin = (const float*)d_in[3];
    const float* W1  = (const float*)d_in[4];
    const float* b1  = (const float*)d_in[5];
    const float* W2  = (const float*)d_in[6];
    const float* b2  = (const float*)d_in[7];
    const float* W3  = (const float*)d_in[8];
    const float* b3  = (const float*)d_in[9];
    float* out = (float*)d_out;

    f16 *A1, *A2, *A3, *W1h, *W2h, *W3h;
    float *pb, *p3;
    cudaGetSymbolAddress((void**)&A1,  g_A1);
    cudaGetSymbolAddress((void**)&A2,  g_A2);
    cudaGetSymbolAddress((void**)&A3,  g_A3);
    cudaGetSymbolAddress((void**)&W1h, g_W1h);
    cudaGetSymbolAddress((void**)&W2h, g_W2h);
    cudaGetSymbolAddress((void**)&W3h, g_W3h);
    cudaGetSymbolAddress((void**)&pb,  g_pb);
    cudaGetSymbolAddress((void**)&p3,  g_p3);

    const int prep_sm = (int)PREP_SMEM;
    cudaFuncSetAttribute(prep_all,  cudaFuncAttributeMaxDynamicSharedMemorySize, prep_sm);
    cudaFuncSetAttribute(ect_final, cudaFuncAttributeMaxDynamicSharedMemorySize, prep_sm);
    cudaFuncSetAttribute(gemm_mma<16, 5>, cudaFuncAttributeMaxDynamicSharedMemorySize, GMEM_SM);
    cudaFuncSetAttribute(gemm_mma<2, 1>,  cudaFuncAttributeMaxDynamicSharedMemorySize, GMEM_SM);

    prep_all<<<2304, 256, prep_sm>>>(x, V, lin, W1, W1h, A1);

    // GEMM1 (256 CTAs) + piggybacked W2 (512) and W3 (64) conversion CTAs
    gemm_mma<16, 5><<<256 + 576, 256, GMEM_SM>>>(A1, W1h, pb, 4096, 4096, 256,
                                                 W2, W2h, W3, W3h);
    reduce_tanh<<<4096, 256>>>(pb, b1, A2);
    gemm_mma<16, 5><<<256, 256, GMEM_SM>>>(A2, W2h, pb, 4096, 4096, 256,
                                           nullptr, nullptr, nullptr, nullptr);
    reduce_tanh<<<4096, 256>>>(pb, b2, A3);
    gemm_mma<2, 1><<<128, 256, GMEM_SM>>>(A3, W3h, p3, 256, 256, 128,
                                          nullptr, nullptr, nullptr, nullptr);

    ect_final<<<256, 256, prep_sm>>>(p3, b3, V, lin, out);
}